// round 1
// baseline (speedup 1.0000x reference)
#include <cuda_runtime.h>

// Problem constants
#define Bn 65536
#define Cn 128
#define Dn 32
#define Kn 10
#define NAUG 33           // augmented dimension: (z, 1)
#define NPAIR 64          // cluster pairs (C/2)
#define UPAD 612          // padded triangular size of 33x33 (rows padded to mult of 4)
#define BLK 128

// Precomputed cluster-pair-interleaved augmented triangular matrices.
// g_U[p][e] = { M_{2p}[e], M_{2p+1}[e] } where M is the 33x33 symmetric form:
//   M[i][i] = Sinv[i][i]            (i < 32)
//   M[i][j] = 2*Sinv[i][j]          (i < j < 32)
//   M[i][32] = -2*(Sinv mu)[i]      (i < 32)
//   M[32][32] = mu' Sinv mu
// so that d2 = w' M w (upper-tri sum) with w = (z, 1).
__device__ float2 g_U[NPAIR][UPAD];
__device__ int g_cls[Cn];

// ---------- packed f32x2 helpers ----------
__device__ __forceinline__ unsigned long long ffma2(unsigned long long a,
                                                    unsigned long long b,
                                                    unsigned long long c) {
    unsigned long long d;
    asm("fma.rn.f32x2 %0, %1, %2, %3;" : "=l"(d) : "l"(a), "l"(b), "l"(c));
    return d;
}
__device__ __forceinline__ unsigned long long fadd2(unsigned long long a,
                                                    unsigned long long b) {
    unsigned long long d;
    asm("add.rn.f32x2 %0, %1, %2;" : "=l"(d) : "l"(a), "l"(b));
    return d;
}
__device__ __forceinline__ unsigned long long fdup(float v) {
    unsigned long long d;
    asm("mov.b64 %0, {%1, %1};" : "=l"(d) : "f"(v));
    return d;
}

// ---------- precompute kernel: build g_U and g_cls ----------
__global__ void prep_kernel(const float* __restrict__ mu,
                            const float* __restrict__ S,
                            const int* __restrict__ lab) {
    const int p = blockIdx.x;      // pair index 0..63
    const int c0 = 2 * p;
    const int tid = threadIdx.x;   // 64 threads

    __shared__ float mus[2][Dn];
    __shared__ float Sm[2][Dn];
    __shared__ float t3s[2];

    {
        int h = tid >> 5, d = tid & 31;
        mus[h][d] = mu[(c0 + h) * Dn + d];
    }
    __syncthreads();
    {
        int h = tid >> 5, d = tid & 31;
        int c = c0 + h;
        float s = 0.f;
#pragma unroll
        for (int e = 0; e < Dn; e++)
            s += S[((c * Dn + d) * Dn) + e] * mus[h][e];
        Sm[h][d] = s;
    }
    __syncthreads();
    if (tid < 2) {
        float s = 0.f;
        for (int d = 0; d < Dn; d++) s += mus[tid][d] * Sm[tid][d];
        t3s[tid] = s;
        // decode one-hot class label
        int c = c0 + tid;
        int k = 0;
        for (int kk = 0; kk < Kn; kk++)
            if (lab[c * Kn + kk] != 0) k = kk;
        g_cls[c] = k;
    }
    __syncthreads();

    int e = 0;
    for (int i = 0; i < NAUG; i++) {
        int len = NAUG - i;
        int plen = (len + 3) & ~3;
        for (int jr = tid; jr < plen; jr += blockDim.x) {
            int j = i + jr;
            float v0 = 0.f, v1 = 0.f;
            if (jr < len) {
                if (j < Dn) {  // i <= j < 32
                    float m = (i == j) ? 1.f : 2.f;
                    v0 = m * S[((c0 * Dn + i) * Dn) + j];
                    v1 = m * S[(((c0 + 1) * Dn + i) * Dn) + j];
                } else if (i < Dn) {  // j == 32
                    v0 = -2.f * Sm[0][i];
                    v1 = -2.f * Sm[1][i];
                } else {  // i == j == 32
                    v0 = t3s[0];
                    v1 = t3s[1];
                }
            }
            g_U[p][e + jr] = make_float2(v0, v1);
        }
        e += plen;
    }
}

// ---------- main kernel: one data row per thread, 2 clusters per iteration ----------
__global__ void __launch_bounds__(BLK, 4)
main_kernel(const float* __restrict__ data, float* __restrict__ out) {
    const int tid = threadIdx.x;
    const int b = blockIdx.x * BLK + tid;

    __shared__ float labAcc[Kn * BLK];  // [k][tid] -> bank-conflict-free
    __shared__ int clsS[Cn];

#pragma unroll
    for (int k = 0; k < Kn; k++) labAcc[k * BLK + tid] = 0.f;
    clsS[tid] = g_cls[tid];  // BLK == Cn == 128
    __syncthreads();

    // load z, pre-duplicate into f32x2 lanes; zz[32] = {1,1} (augmentation)
    unsigned long long zz[NAUG];
    const float4* dp = (const float4*)(data + (long long)b * Dn);
#pragma unroll
    for (int q = 0; q < 8; q++) {
        float4 v = dp[q];
        zz[4 * q + 0] = fdup(v.x);
        zz[4 * q + 1] = fdup(v.y);
        zz[4 * q + 2] = fdup(v.z);
        zz[4 * q + 3] = fdup(v.w);
    }
    zz[32] = fdup(1.f);

    float sum = 0.f;
    float gmax = -1.f;
    int cmax = 0;

    for (int p = 0; p < NPAIR; p++) {
        const float2* Up = g_U[p];
        unsigned long long d2 = 0ULL;
        int e = 0;
#pragma unroll
        for (int i = 0; i < NAUG; i++) {
            const int len = NAUG - i;
            const int plen = (len + 3) & ~3;
            unsigned long long r0 = 0ULL, r1 = 0ULL;
#pragma unroll
            for (int jr = 0; jr < plen; jr += 2) {
                ulonglong2 uu = *(const ulonglong2*)(Up + e + jr);
                int j0 = i + jr;     if (j0 > 32) j0 = 32;  // padded lanes: u==0
                int j1 = i + jr + 1; if (j1 > 32) j1 = 32;
                r0 = ffma2(uu.x, zz[j0], r0);
                r1 = ffma2(uu.y, zz[j1], r1);
            }
            d2 = ffma2(zz[i], fadd2(r0, r1), d2);
            e += plen;
        }

        float d0, d1;
        asm("mov.b64 {%0, %1}, %2;" : "=f"(d0), "=f"(d1) : "l"(d2));
        float g0 = __expf(-0.5f * d0);
        float g1 = __expf(-0.5f * d1);
        sum += g0 + g1;

        const int c0 = 2 * p;
        if (g0 > gmax) { gmax = g0; cmax = c0; }
        if (g1 > gmax) { gmax = g1; cmax = c0 + 1; }
        labAcc[clsS[c0] * BLK + tid] += g0;
        labAcc[clsS[c0 + 1] * BLK + tid] += g1;
    }

    // epilogue: normalize, write label_scores, preds, clusters
    const float inv = 1.f / (sum + 1e-12f);
    float best = -1.f;
    int kb = 0;
#pragma unroll
    for (int k = 0; k < Kn; k++) {
        float ls = labAcc[k * BLK + tid] * inv;
        out[b * Kn + k] = ls;
        if (ls > best) { best = ls; kb = k; }
    }
    out[Bn * Kn + b] = (float)kb;
    out[Bn * Kn + Bn + b] = (float)cmax;
}

extern "C" void kernel_launch(void* const* d_in, const int* in_sizes, int n_in,
                              void* d_out, int out_size) {
    const float* data = (const float*)d_in[0];        // [B, D]
    const float* mu   = (const float*)d_in[1];        // [C, D]
    const float* Sinv = (const float*)d_in[2];        // [C, D, D]
    const int*   lab  = (const int*)d_in[3];          // [C, K] one-hot int32
    float* out = (float*)d_out;

    prep_kernel<<<NPAIR, 64>>>(mu, Sinv, lab);
    main_kernel<<<Bn / BLK, BLK>>>(data, out);
}

// round 2
// speedup vs baseline: 1.4651x; 1.4651x over previous
#include <cuda_runtime.h>

// ---------------- problem constants ----------------
#define Bn 65536
#define Cn 128
#define Dn 32
#define Kn 10
#define NAUG 33        // augmented dim (z, 1)
#define KTRI 561       // triangular size of 33x33
#define KPAD 576       // padded to 9 chunks of 64
#define KC 64          // k-chunk
#define NCHUNK 9
#define ROWS 64        // data rows per block
#define THREADS 256

// U table, k-major across clusters: g_Upk[k*128 + c]
__device__ float g_Upk[KPAD * Cn];
__device__ int g_ij[KPAD];   // packed (i | j<<8) triangular index per k
__device__ int g_cls[Cn];

// ---------------- packed f32x2 helpers ----------------
typedef unsigned long long ull;
__device__ __forceinline__ ull ffma2(ull a, ull b, ull c) {
    ull d;
    asm("fma.rn.f32x2 %0, %1, %2, %3;" : "=l"(d) : "l"(a), "l"(b), "l"(c));
    return d;
}
__device__ __forceinline__ void cp16(void* sdst, const void* gsrc) {
    unsigned sa = (unsigned)__cvta_generic_to_shared(sdst);
    asm volatile("cp.async.cg.shared.global [%0], [%1], 16;" :: "r"(sa), "l"(gsrc));
}

// ---------------- prep: build U (k-major), ij table, labels ----------------
__global__ void prep_kernel(const float* __restrict__ mu,
                            const float* __restrict__ S,
                            const int* __restrict__ lab) {
    const int c = blockIdx.x;      // cluster
    const int t = threadIdx.x;     // 32 threads
    __shared__ float mus[Dn], Sm[Dn];

    mus[t] = mu[c * Dn + t];
    __syncwarp();
    float s = 0.f;
#pragma unroll
    for (int e = 0; e < Dn; e++) s += S[(c * Dn + t) * Dn + e] * mus[e];
    Sm[t] = s;
    __syncwarp();
    float t3 = mus[t] * Sm[t];
#pragma unroll
    for (int m = 16; m >= 1; m >>= 1) t3 += __shfl_xor_sync(0xffffffffu, t3, m);

    if (t == 0) {
        int cl = 0;
        for (int k = 0; k < Kn; k++) if (lab[c * Kn + k] != 0) cl = k;
        g_cls[c] = cl;
    }

    for (int k = t; k < KPAD; k += 32) {
        int i = 0, rem = k;
        while (i < NAUG && rem >= NAUG - i) { rem -= NAUG - i; i++; }
        float v; int ii, jj;
        if (i >= NAUG) { v = 0.f; ii = 32; jj = 32; }   // pad
        else {
            int j = i + rem; ii = i; jj = j;
            if (j < Dn)      v = ((i == j) ? 1.f : 2.f) * S[(c * Dn + i) * Dn + j];
            else if (i < Dn) v = -2.f * Sm[i];
            else             v = t3;
        }
        g_Upk[k * Cn + c] = v;
        if (c == 0) g_ij[k] = ii | (jj << 8);
    }
}

// ---------------- smem layout offsets (bytes) ----------------
#define OFF_A    0                        // float2 [KC*ROWS]        32768
#define OFF_B    32768                    // float  [2][KC*Cn]       65536
#define OFF_Z    98304                    // float  [33*65]           8580
#define OFF_IJ   106884                   // int    [KPAD]            2304
#define OFF_LAB  109188                   // float  [Kn*ROWS]         2560
#define OFF_SUM  111748                   // float  [ROWS]             256
#define OFF_MIDX 112004                   // int    [ROWS]             256
#define OFF_CLS  112260                   // int    [Cn]               512
#define SMEM_SZ  112772

// ---------------- main kernel ----------------
__global__ void __launch_bounds__(THREADS, 2)
main_kernel(const float* __restrict__ data, float* __restrict__ out) {
    extern __shared__ char sm_[];
    float2* A_s   = (float2*)(sm_ + OFF_A);
    float*  B_s   = (float*)(sm_ + OFF_B);
    float*  z_s   = (float*)(sm_ + OFF_Z);
    int*    ij_s  = (int*)(sm_ + OFF_IJ);
    float*  lab_s = (float*)(sm_ + OFF_LAB);
    float*  sum_s = (float*)(sm_ + OFF_SUM);
    int*    midx_s= (int*)(sm_ + OFF_MIDX);
    int*    cls_s = (int*)(sm_ + OFF_CLS);

    const int tid = threadIdx.x;
    const int bbase = blockIdx.x * ROWS;
    const int cg = tid & 15;   // 16 cluster-groups x 8 clusters
    const int rg = tid >> 4;   // 16 row-groups x 4 rows

    if (tid < Cn) cls_s[tid] = g_cls[tid];
    for (int i = tid; i < Kn * ROWS; i += THREADS) lab_s[i] = 0.f;
    for (int i = tid; i < KPAD; i += THREADS) ij_s[i] = g_ij[i];

    // coalesced load of z, stored transposed [d][row] with pad-65 stride
    {
        int d = tid & 31, r0 = tid >> 5;
        for (int r = r0; r < ROWS; r += 8)
            z_s[d * 65 + r] = data[(size_t)(bbase + r) * Dn + d];
        if (tid < ROWS) z_s[32 * 65 + tid] = 1.f;
    }

    // prefetch B chunk 0
    {
        const char* src = (const char*)g_Upk;
        for (int o = 0; o < 8; o++) {
            int e = tid + o * THREADS;        // 0..2047 x 16B
            cp16((char*)B_s + e * 16, src + e * 16);
        }
        asm volatile("cp.async.commit_group;");
    }
    __syncthreads();   // z_s / ij_s ready

    ull acc[16];
#pragma unroll
    for (int i = 0; i < 16; i++) acc[i] = 0ull;

    for (int ch = 0; ch < NCHUNK; ch++) {
        const int cur = ch & 1;
        if (ch + 1 < NCHUNK) {
            const char* src = (const char*)(g_Upk + (ch + 1) * KC * Cn);
            char* dst = (char*)(B_s + (1 - cur) * KC * Cn);
            for (int o = 0; o < 8; o++) {
                int e = tid + o * THREADS;
                cp16(dst + e * 16, src + e * 16);
            }
            asm volatile("cp.async.commit_group;");
        }
        // build A chunk: w = z_i * z_j, stored duplicated {w,w}
        const int k0 = ch * KC;
#pragma unroll
        for (int it = 0; it < 16; it++) {
            int cell = tid + it * THREADS;        // kk*64 + row
            int kk = cell >> 6, row = cell & 63;
            int ij = ij_s[k0 + kk];
            float w = z_s[(ij & 255) * 65 + row] * z_s[(ij >> 8) * 65 + row];
            A_s[cell] = make_float2(w, w);
        }
        if (ch + 1 < NCHUNK) asm volatile("cp.async.wait_group 1;");
        else                 asm volatile("cp.async.wait_group 0;");
        __syncthreads();

        const float* Bc = B_s + cur * KC * Cn;
#pragma unroll 4
        for (int kk = 0; kk < KC; kk++) {
            ulonglong2 av0 = *(const ulonglong2*)(A_s + kk * 64 + rg * 4);
            ulonglong2 av1 = *(const ulonglong2*)(A_s + kk * 64 + rg * 4 + 2);
            ulonglong2 bv0 = *(const ulonglong2*)(Bc + kk * 128 + cg * 8);
            ulonglong2 bv1 = *(const ulonglong2*)(Bc + kk * 128 + cg * 8 + 4);
            ull a0 = av0.x, a1 = av0.y, a2 = av1.x, a3 = av1.y;
            ull b0 = bv0.x, b1 = bv0.y, b2 = bv1.x, b3 = bv1.y;
            acc[0]  = ffma2(a0, b0, acc[0]);
            acc[1]  = ffma2(a0, b1, acc[1]);
            acc[2]  = ffma2(a0, b2, acc[2]);
            acc[3]  = ffma2(a0, b3, acc[3]);
            acc[4]  = ffma2(a1, b0, acc[4]);
            acc[5]  = ffma2(a1, b1, acc[5]);
            acc[6]  = ffma2(a1, b2, acc[6]);
            acc[7]  = ffma2(a1, b3, acc[7]);
            acc[8]  = ffma2(a2, b0, acc[8]);
            acc[9]  = ffma2(a2, b1, acc[9]);
            acc[10] = ffma2(a2, b2, acc[10]);
            acc[11] = ffma2(a2, b3, acc[11]);
            acc[12] = ffma2(a3, b0, acc[12]);
            acc[13] = ffma2(a3, b1, acc[13]);
            acc[14] = ffma2(a3, b2, acc[14]);
            acc[15] = ffma2(a3, b3, acc[15]);
        }
        __syncthreads();
    }

    // ---------------- epilogue ----------------
#pragma unroll
    for (int r = 0; r < 4; r++) {
        const int row = rg * 4 + r;
        float s = 0.f, mv = -1.f;
        int mi = 0;
#pragma unroll
        for (int q = 0; q < 4; q++) {
            float d0, d1;
            asm("mov.b64 {%0, %1}, %2;" : "=f"(d0), "=f"(d1) : "l"(acc[r * 4 + q]));
            float g0 = __expf(-0.5f * d0);
            float g1 = __expf(-0.5f * d1);
            int c0 = cg * 8 + q * 2;
            s += g0 + g1;
            if (g0 > mv) { mv = g0; mi = c0; }
            if (g1 > mv) { mv = g1; mi = c0 + 1; }
            atomicAdd(&lab_s[cls_s[c0] * ROWS + row], g0);
            atomicAdd(&lab_s[cls_s[c0 + 1] * ROWS + row], g1);
        }
        // reduce across the 16 lanes sharing this row (xor<=8 stays in half)
#pragma unroll
        for (int m = 8; m >= 1; m >>= 1) {
            s += __shfl_xor_sync(0xffffffffu, s, m);
            float ov = __shfl_xor_sync(0xffffffffu, mv, m);
            int oi = __shfl_xor_sync(0xffffffffu, mi, m);
            if (ov > mv || (ov == mv && oi < mi)) { mv = ov; mi = oi; }
        }
        if (cg == 0) { sum_s[row] = s; midx_s[row] = mi; }
    }
    __syncthreads();

    if (tid < ROWS) {
        const int row = tid;
        const size_t b = (size_t)bbase + row;
        float inv = 1.f / (sum_s[row] + 1e-12f);
        float best = -1.f;
        int kb = 0;
#pragma unroll
        for (int k = 0; k < Kn; k++) {
            float ls = lab_s[k * ROWS + row] * inv;
            out[b * Kn + k] = ls;
            if (ls > best) { best = ls; kb = k; }
        }
        out[(size_t)Bn * Kn + b] = (float)kb;
        out[(size_t)Bn * Kn + Bn + b] = (float)midx_s[row];
    }
}

extern "C" void kernel_launch(void* const* d_in, const int* in_sizes, int n_in,
                              void* d_out, int out_size) {
    const float* data = (const float*)d_in[0];   // [B, D]
    const float* mu   = (const float*)d_in[1];   // [C, D]
    const float* Sinv = (const float*)d_in[2];   // [C, D, D]
    const int*   lab  = (const int*)d_in[3];     // [C, K]
    float* out = (float*)d_out;

    static int smem_set = 0;
    if (!smem_set) {
        cudaFuncSetAttribute(main_kernel,
                             cudaFuncAttributeMaxDynamicSharedMemorySize, SMEM_SZ);
        smem_set = 1;
    }
    prep_kernel<<<Cn, 32>>>(mu, Sinv, lab);
    main_kernel<<<Bn / ROWS, THREADS, SMEM_SZ>>>(data, out);
}

// round 3
// speedup vs baseline: 2.1215x; 1.4480x over previous
#include <cuda_runtime.h>

// ---------------- problem constants ----------------
#define Bn 65536
#define Cn 128
#define Dn 32
#define Kn 10
#define NAUG 33        // augmented dim (z, 1)
#define KPAD 576       // padded triangular size (18 chunks of 32)
#define KC 32          // k-chunk
#define NCHUNK 18
#define ROWS 128       // data rows per block
#define THREADS 256

// U table, k-major across clusters: g_Upk[k*128 + c]
__device__ float g_Upk[KPAD * Cn];
__device__ int g_ij[KPAD];   // packed (i | j<<8) triangular index per k
__device__ int g_cls[Cn];

typedef unsigned long long ull;
__device__ __forceinline__ ull ffma2(ull a, ull b, ull c) {
    ull d;
    asm("fma.rn.f32x2 %0, %1, %2, %3;" : "=l"(d) : "l"(a), "l"(b), "l"(c));
    return d;
}
__device__ __forceinline__ ull fdup(float v) {
    ull d;
    asm("mov.b64 %0, {%1, %1};" : "=l"(d) : "f"(v));
    return d;
}
__device__ __forceinline__ void cp16(void* sdst, const void* gsrc) {
    unsigned sa = (unsigned)__cvta_generic_to_shared(sdst);
    asm volatile("cp.async.cg.shared.global [%0], [%1], 16;" :: "r"(sa), "l"(gsrc));
}

// ---------------- prep: build U (k-major), ij table, labels ----------------
__global__ void prep_kernel(const float* __restrict__ mu,
                            const float* __restrict__ S,
                            const int* __restrict__ lab) {
    const int c = blockIdx.x;      // cluster
    const int t = threadIdx.x;     // 32 threads
    __shared__ float mus[Dn], Sm[Dn];

    mus[t] = mu[c * Dn + t];
    __syncwarp();
    float s = 0.f;
#pragma unroll
    for (int e = 0; e < Dn; e++) s += S[(c * Dn + t) * Dn + e] * mus[e];
    Sm[t] = s;
    __syncwarp();
    float t3 = mus[t] * Sm[t];
#pragma unroll
    for (int m = 16; m >= 1; m >>= 1) t3 += __shfl_xor_sync(0xffffffffu, t3, m);

    if (t == 0) {
        int cl = 0;
        for (int k = 0; k < Kn; k++) if (lab[c * Kn + k] != 0) cl = k;
        g_cls[c] = cl;
    }

    for (int k = t; k < KPAD; k += 32) {
        int i = 0, rem = k;
        while (i < NAUG && rem >= NAUG - i) { rem -= NAUG - i; i++; }
        float v; int ii, jj;
        if (i >= NAUG) { v = 0.f; ii = 32; jj = 32; }   // pad
        else {
            int j = i + rem; ii = i; jj = j;
            if (j < Dn)      v = ((i == j) ? 1.f : 2.f) * S[(c * Dn + i) * Dn + j];
            else if (i < Dn) v = -2.f * Sm[i];
            else             v = t3;
        }
        g_Upk[k * Cn + c] = v;
        if (c == 0) g_ij[k] = ii | (jj << 8);
    }
}

// ---------------- smem layout (bytes) ----------------
#define OFF_A    0            // float [KC*ROWS]           16384
#define OFF_B    16384        // float [2][KC*Cn]          32768
#define OFF_Z    49152        // float [33*129]            17028
#define OFF_IJ   66180        // int   [KPAD]               2304
#define OFF_LAB  68484        // float [Kn*ROWS]            5120
#define OFF_SUM  73604        // float [ROWS]                512
#define OFF_MIDX 74116        // int   [ROWS]                512
#define OFF_CLS  74628        // int   [Cn]                  512
#define SMEM_SZ  75140

// ---------------- main kernel: 8 rows x 8 cols per thread ----------------
__global__ void __launch_bounds__(THREADS, 2)
main_kernel(const float* __restrict__ data, float* __restrict__ out) {
    extern __shared__ char sm_[];
    float*  A_s   = (float*)(sm_ + OFF_A);
    float*  B_s   = (float*)(sm_ + OFF_B);
    float*  z_s   = (float*)(sm_ + OFF_Z);
    int*    ij_s  = (int*)(sm_ + OFF_IJ);
    float*  lab_s = (float*)(sm_ + OFF_LAB);
    float*  sum_s = (float*)(sm_ + OFF_SUM);
    int*    midx_s= (int*)(sm_ + OFF_MIDX);
    int*    cls_s = (int*)(sm_ + OFF_CLS);

    const int tid = threadIdx.x;
    const int bbase = blockIdx.x * ROWS;
    const int cg = tid & 15;   // 16 col-groups x 8 cols
    const int rg = tid >> 4;   // 16 row-groups x 8 rows

    if (tid < Cn) cls_s[tid] = g_cls[tid];
    for (int i = tid; i < Kn * ROWS; i += THREADS) lab_s[i] = 0.f;
    for (int i = tid; i < KPAD; i += THREADS) ij_s[i] = g_ij[i];

    // coalesced load of z, stored transposed [d][row], stride 129
    for (int idx = tid; idx < ROWS * Dn; idx += THREADS) {
        int row = idx >> 5, d = idx & 31;
        z_s[d * 129 + row] = data[(size_t)(bbase + row) * Dn + d];
    }
    if (tid < ROWS) z_s[32 * 129 + tid] = 1.f;

    // prefetch B chunk 0 (KC*Cn*4 = 16KB = 1024 x 16B)
    {
        const char* src = (const char*)g_Upk;
        for (int o = 0; o < 4; o++) {
            int e = tid + o * THREADS;
            cp16((char*)B_s + e * 16, src + e * 16);
        }
        asm volatile("cp.async.commit_group;");
    }
    __syncthreads();   // z_s / ij_s ready

    ull acc[32];
#pragma unroll
    for (int i = 0; i < 32; i++) acc[i] = 0ull;

    for (int ch = 0; ch < NCHUNK; ch++) {
        const int cur = ch & 1;
        if (ch + 1 < NCHUNK) {
            const char* src = (const char*)(g_Upk + (ch + 1) * KC * Cn);
            char* dst = (char*)(B_s + (1 - cur) * KC * Cn);
            for (int o = 0; o < 4; o++) {
                int e = tid + o * THREADS;
                cp16(dst + e * 16, src + e * 16);
            }
            asm volatile("cp.async.commit_group;");
        }
        // build A chunk: w = z_i * z_j (plain float, [kk][row])
        const int k0 = ch * KC;
#pragma unroll
        for (int it = 0; it < 16; it++) {
            int cell = tid + it * THREADS;        // kk*128 + row
            int kk = cell >> 7, row = cell & 127;
            int ij = ij_s[k0 + kk];
            A_s[cell] = z_s[(ij & 255) * 129 + row] * z_s[(ij >> 8) * 129 + row];
        }
        if (ch + 1 < NCHUNK) asm volatile("cp.async.wait_group 1;");
        else                 asm volatile("cp.async.wait_group 0;");
        __syncthreads();

        const float* Bc = B_s + cur * KC * Cn;
#pragma unroll 2
        for (int kk = 0; kk < KC; kk++) {
            const float* Ak = A_s + kk * 128 + rg * 8;
            float4 a0 = *(const float4*)Ak;
            float4 a1 = *(const float4*)(Ak + 4);
            ull ad[8];
            ad[0] = fdup(a0.x); ad[1] = fdup(a0.y);
            ad[2] = fdup(a0.z); ad[3] = fdup(a0.w);
            ad[4] = fdup(a1.x); ad[5] = fdup(a1.y);
            ad[6] = fdup(a1.z); ad[7] = fdup(a1.w);
            const float* Bk = Bc + kk * 128 + cg * 8;
            ulonglong2 bv0 = *(const ulonglong2*)Bk;
            ulonglong2 bv1 = *(const ulonglong2*)(Bk + 4);
            ull b0 = bv0.x, b1 = bv0.y, b2 = bv1.x, b3 = bv1.y;
#pragma unroll
            for (int r = 0; r < 8; r++) {
                acc[r * 4 + 0] = ffma2(ad[r], b0, acc[r * 4 + 0]);
                acc[r * 4 + 1] = ffma2(ad[r], b1, acc[r * 4 + 1]);
                acc[r * 4 + 2] = ffma2(ad[r], b2, acc[r * 4 + 2]);
                acc[r * 4 + 3] = ffma2(ad[r], b3, acc[r * 4 + 3]);
            }
        }
        __syncthreads();
    }

    // ---------------- epilogue ----------------
#pragma unroll
    for (int r = 0; r < 8; r++) {
        const int row = rg * 8 + r;
        float s = 0.f, mv = -1.f;
        int mi = 0;
#pragma unroll
        for (int q = 0; q < 4; q++) {
            float d0, d1;
            asm("mov.b64 {%0, %1}, %2;" : "=f"(d0), "=f"(d1) : "l"(acc[r * 4 + q]));
            float g0 = __expf(-0.5f * d0);
            float g1 = __expf(-0.5f * d1);
            int c0 = cg * 8 + q * 2;
            s += g0 + g1;
            if (g0 > mv) { mv = g0; mi = c0; }
            if (g1 > mv) { mv = g1; mi = c0 + 1; }
            atomicAdd(&lab_s[cls_s[c0] * ROWS + row], g0);
            atomicAdd(&lab_s[cls_s[c0 + 1] * ROWS + row], g1);
        }
        // reduce across the 16 cg lanes sharing this row
#pragma unroll
        for (int m = 8; m >= 1; m >>= 1) {
            s += __shfl_xor_sync(0xffffffffu, s, m);
            float ov = __shfl_xor_sync(0xffffffffu, mv, m);
            int oi = __shfl_xor_sync(0xffffffffu, mi, m);
            if (ov > mv || (ov == mv && oi < mi)) { mv = ov; mi = oi; }
        }
        if (cg == 0) { sum_s[row] = s; midx_s[row] = mi; }
    }
    __syncthreads();

    if (tid < ROWS) {
        const int row = tid;
        const size_t b = (size_t)bbase + row;
        float inv = 1.f / (sum_s[row] + 1e-12f);
        float best = -1.f;
        int kb = 0;
#pragma unroll
        for (int k = 0; k < Kn; k++) {
            float ls = lab_s[k * ROWS + row] * inv;
            out[b * Kn + k] = ls;
            if (ls > best) { best = ls; kb = k; }
        }
        out[(size_t)Bn * Kn + b] = (float)kb;
        out[(size_t)Bn * Kn + Bn + b] = (float)midx_s[row];
    }
}

extern "C" void kernel_launch(void* const* d_in, const int* in_sizes, int n_in,
                              void* d_out, int out_size) {
    const float* data = (const float*)d_in[0];   // [B, D]
    const float* mu   = (const float*)d_in[1];   // [C, D]
    const float* Sinv = (const float*)d_in[2];   // [C, D, D]
    const int*   lab  = (const int*)d_in[3];     // [C, K]
    float* out = (float*)d_out;

    static int smem_set = 0;
    if (!smem_set) {
        cudaFuncSetAttribute(main_kernel,
                             cudaFuncAttributeMaxDynamicSharedMemorySize, SMEM_SZ);
        smem_set = 1;
    }
    prep_kernel<<<Cn, 32>>>(mu, Sinv, lab);
    main_kernel<<<Bn / ROWS, THREADS, SMEM_SZ>>>(data, out);
}

// round 5
// speedup vs baseline: 3.6973x; 1.7428x over previous
#include <cuda_runtime.h>
#include <cuda_fp16.h>

// ---------------- problem constants ----------------
#define Bn 65536
#define Cn 128
#define Dn 32
#define Kn 10
#define NAUG 33
#define KPAD 576          // padded triangular size (9 chunks of 64)
#define KC 64
#define NCH 9
#define ROWS 128
#define THREADS 256
#define TILE_B 16384      // 128 rows x 64 k x fp16 (128B rows, SW128)

#define SWZ(o) ((o) ^ (((o) >> 3) & 0x70))

// pre-split fp16 U tiles, pre-swizzled: [split][chunk][16KB]
__device__ __align__(16) unsigned char g_Uh[2][NCH][TILE_B];
__device__ int g_ij[KPAD];     // (i | j<<8)
__device__ int g_cls[Cn];

// ---------------- helpers ----------------
static __device__ __forceinline__ unsigned smem_u32(const void* p) {
    unsigned a;
    asm("{ .reg .u64 t; cvta.to.shared.u64 t, %1; cvt.u32.u64 %0, t; }"
        : "=r"(a) : "l"(p));
    return a;
}
static __device__ __forceinline__ void cp16(unsigned sdst, const void* gsrc) {
    asm volatile("cp.async.cg.shared.global [%0], [%1], 16;" :: "r"(sdst), "l"(gsrc));
}
static __device__ __forceinline__ void ldsm4(unsigned base, int row0, int kb,
                                             int lane, unsigned* r) {
    unsigned off = (unsigned)((row0 + (lane & 15)) * 128 + kb + ((lane >> 4) << 4));
    unsigned addr = base + SWZ(off);
    asm volatile("ldmatrix.sync.aligned.m8n8.x4.shared.b16 {%0,%1,%2,%3}, [%4];"
                 : "=r"(r[0]), "=r"(r[1]), "=r"(r[2]), "=r"(r[3]) : "r"(addr));
}
#define MMA16816(C, A, b0, b1) \
    asm volatile("mma.sync.aligned.m16n8k16.row.col.f32.f16.f16.f32 " \
        "{%0,%1,%2,%3}, {%4,%5,%6,%7}, {%8,%9}, {%0,%1,%2,%3};" \
        : "+f"((C)[0]), "+f"((C)[1]), "+f"((C)[2]), "+f"((C)[3]) \
        : "r"((A)[0]), "r"((A)[1]), "r"((A)[2]), "r"((A)[3]), "r"(b0), "r"(b1))

// ---------------- prep: split U into 2 fp16 tiles (pre-swizzled) ----------------
__global__ void prep_kernel(const float* __restrict__ mu,
                            const float* __restrict__ S,
                            const int* __restrict__ lab) {
    const int c = blockIdx.x;
    const int t = threadIdx.x;   // 32
    __shared__ float mus[Dn], Sm[Dn];

    mus[t] = mu[c * Dn + t];
    __syncwarp();
    float s = 0.f;
#pragma unroll
    for (int e = 0; e < Dn; e++) s += S[(c * Dn + t) * Dn + e] * mus[e];
    Sm[t] = s;
    __syncwarp();
    float t3 = mus[t] * Sm[t];
#pragma unroll
    for (int m = 16; m >= 1; m >>= 1) t3 += __shfl_xor_sync(0xffffffffu, t3, m);

    if (t == 0) {
        int cl = 0;
        for (int k = 0; k < Kn; k++) if (lab[c * Kn + k] != 0) cl = k;
        g_cls[c] = cl;
    }

    for (int k = t; k < KPAD; k += 32) {
        int i = 0, rem = k;
        while (i < NAUG && rem >= NAUG - i) { rem -= NAUG - i; i++; }
        float v; int ii, jj;
        if (i >= NAUG) { v = 0.f; ii = 32; jj = 32; }
        else {
            int j = i + rem; ii = i; jj = j;
            if (j < Dn)      v = ((i == j) ? 1.f : 2.f) * S[(c * Dn + i) * Dn + j];
            else if (i < Dn) v = -2.f * Sm[i];
            else             v = t3;
        }
        if (c == 0) g_ij[k] = ii | (jj << 8);

        __half h0 = __float2half_rn(v);
        float r = v - __half2float(h0);
        __half h1 = __float2half_rn(r);

        int ch = k >> 6, kk = k & 63;
        int sw = SWZ(c * 128 + kk * 2);
        *(__half*)&g_Uh[0][ch][sw] = h0;
        *(__half*)&g_Uh[1][ch][sw] = h1;
    }
}

// ---------------- smem layout (bytes) ----------------
#define OFF_Z    0          // 33*129*4 = 17028 -> 17152
#define OFF_IJ   17152      // 2304 -> 19456
#define OFF_CLS  19456      // 512 -> 19968
#define OFF_LAB  19968      // 10*128*4 = 5120 -> 25088
#define OFF_T    25600      // A0,A1 (32KB) + B double (64KB) = 96KB
#define SMEM_SZ  123904

// ---------------- main kernel ----------------
__global__ void __launch_bounds__(THREADS, 1)
main_kernel(const float* __restrict__ data, float* __restrict__ out) {
    extern __shared__ char sm_[];
    int*   ij_s  = (int*)(sm_ + OFF_IJ);
    int*   cls_s = (int*)(sm_ + OFF_CLS);
    float* lab_s = (float*)(sm_ + OFF_LAB);
    float* z_s   = (float*)(sm_ + OFF_Z);

    const int tid = threadIdx.x;
    const int wid = tid >> 5;
    const int lane = tid & 31;
    const int mw = wid >> 1;          // 0..3 -> rows mw*32
    const int nw = wid & 1;           // 0..1 -> cols nw*64
    const int bbase = blockIdx.x * ROWS;
    const unsigned sbase = smem_u32(sm_);

    const unsigned tA0 = sbase + OFF_T;
    const unsigned tA1 = tA0 + TILE_B;
    const unsigned tBb = tA0 + 2 * TILE_B;   // + buf*32768 + split*16384

    // prologue
    if (tid < Cn) cls_s[tid] = g_cls[tid];
    for (int i = tid; i < Kn * ROWS; i += THREADS) lab_s[i] = 0.f;
    for (int i = tid; i < KPAD; i += THREADS) ij_s[i] = g_ij[i];
    for (int idx = tid; idx < ROWS * Dn; idx += THREADS) {
        int row = idx >> 5, d = idx & 31;
        z_s[d * 129 + row] = data[(size_t)(bbase + row) * Dn + d];
    }
    if (tid < ROWS) z_s[32 * 129 + tid] = 1.f;

    // prefetch B chunk 0 into buf 0
#pragma unroll
    for (int s = 0; s < 2; s++)
        for (int e = tid; e < TILE_B / 16; e += THREADS)
            cp16(tBb + s * TILE_B + e * 16, &g_Uh[s][0][e * 16]);
    asm volatile("cp.async.commit_group;");
    __syncthreads();   // z_s / ij_s ready

    float acc[16][4];
#pragma unroll
    for (int i = 0; i < 16; i++)
#pragma unroll
        for (int q = 0; q < 4; q++) acc[i][q] = 0.f;

    for (int ch = 0; ch < NCH; ch++) {
        const int cur = ch & 1;
        if (ch > 0) __syncthreads();   // prev mma done: A tiles & next B buf free

        if (ch + 1 < NCH) {
            unsigned dst = tBb + (1 - cur) * 2 * TILE_B;
#pragma unroll
            for (int s = 0; s < 2; s++)
                for (int e = tid; e < TILE_B / 16; e += THREADS)
                    cp16(dst + s * TILE_B + e * 16, &g_Uh[s][ch + 1][e * 16]);
            asm volatile("cp.async.commit_group;");
        }

        // build A tiles: w = z_i*z_j, fp16 2-way split, 2 k per thread
        const int k0 = ch * KC;
#pragma unroll
        for (int it = 0; it < 16; it++) {
            int idx = tid + it * THREADS;   // 4096 (row, kpair)
            int kp = idx & 31, row = idx >> 5;
            int ij0 = ij_s[k0 + 2 * kp], ij1 = ij_s[k0 + 2 * kp + 1];
            float w0 = z_s[(ij0 & 255) * 129 + row] * z_s[(ij0 >> 8) * 129 + row];
            float w1 = z_s[(ij1 & 255) * 129 + row] * z_s[(ij1 >> 8) * 129 + row];

            __half h00 = __float2half_rn(w0), h01 = __float2half_rn(w1);
            float r0 = w0 - __half2float(h00);
            float r1 = w1 - __half2float(h01);
            __half2 p0 = __halves2half2(h00, h01);
            __half2 p1 = __halves2half2(__float2half_rn(r0), __float2half_rn(r1));

            unsigned sw = SWZ((unsigned)(row * 128 + kp * 4));
            asm volatile("st.shared.b32 [%0], %1;" :: "r"(tA0 + sw),
                         "r"(*(unsigned*)&p0));
            asm volatile("st.shared.b32 [%0], %1;" :: "r"(tA1 + sw),
                         "r"(*(unsigned*)&p1));
        }
        if (ch + 1 < NCH) asm volatile("cp.async.wait_group 1;");
        else              asm volatile("cp.async.wait_group 0;");
        __syncthreads();

        const unsigned curB = tBb + cur * 2 * TILE_B;
#pragma unroll
        for (int ks = 0; ks < 4; ks++) {
            const int kb = ks * 32;
            unsigned a0[2][4], a1[2][4];
#pragma unroll
            for (int mf = 0; mf < 2; mf++) {
                ldsm4(tA0, mw * 32 + mf * 16, kb, lane, a0[mf]);
                ldsm4(tA1, mw * 32 + mf * 16, kb, lane, a1[mf]);
            }
#pragma unroll
            for (int nf2 = 0; nf2 < 4; nf2++) {
                unsigned b0[4], b1[4];
                ldsm4(curB,          nw * 64 + nf2 * 16, kb, lane, b0);
                ldsm4(curB + TILE_B, nw * 64 + nf2 * 16, kb, lane, b1);
#pragma unroll
                for (int mf = 0; mf < 2; mf++)
#pragma unroll
                    for (int h = 0; h < 2; h++) {
                        float* C = acc[mf * 8 + nf2 * 2 + h];
                        MMA16816(C, a0[mf], b0[h], b0[h + 2]);   // h0*g0
                        MMA16816(C, a0[mf], b1[h], b1[h + 2]);   // h0*g1
                        MMA16816(C, a1[mf], b0[h], b0[h + 2]);   // h1*g0
                    }
            }
        }
    }
    __syncthreads();   // all mma done -> tile smem reusable

    // ---------------- epilogue ----------------
    float* gsm = (float*)(sm_ + OFF_T);   // d2 staging [128][130]
    const int lr = lane >> 2, lc = (lane & 3) * 2;
#pragma unroll
    for (int mf = 0; mf < 2; mf++)
#pragma unroll
        for (int nf = 0; nf < 8; nf++) {
            int row = mw * 32 + mf * 16 + lr;
            int col = nw * 64 + nf * 8 + lc;
            float* C = acc[mf * 8 + nf];
            gsm[row * 130 + col]           = C[0];
            gsm[row * 130 + col + 1]       = C[1];
            gsm[(row + 8) * 130 + col]     = C[2];
            gsm[(row + 8) * 130 + col + 1] = C[3];
        }
    __syncthreads();

    if (tid < ROWS) {
        const int row = tid;
        float sum = 0.f, gmax = -1.f;
        int cmax = 0;
#pragma unroll 4
        for (int c = 0; c < Cn; c++) {
            float d2 = gsm[row * 130 + c];
            float g = __expf(-0.5f * d2);
            sum += g;
            if (g > gmax) { gmax = g; cmax = c; }
            lab_s[cls_s[c] * ROWS + row] += g;   // row-exclusive
        }
        const size_t b = (size_t)bbase + row;
        float inv = 1.f / (sum + 1e-12f);
        float best = -1.f;
        int kb = 0;
#pragma unroll
        for (int k = 0; k < Kn; k++) {
            float ls = lab_s[k * ROWS + row] * inv;
            out[b * Kn + k] = ls;
            if (ls > best) { best = ls; kb = k; }
        }
        out[(size_t)Bn * Kn + b] = (float)kb;
        out[(size_t)Bn * Kn + Bn + b] = (float)cmax;
    }
}

extern "C" void kernel_launch(void* const* d_in, const int* in_sizes, int n_in,
                              void* d_out, int out_size) {
    const float* data = (const float*)d_in[0];   // [B, D]
    const float* mu   = (const float*)d_in[1];   // [C, D]
    const float* Sinv = (const float*)d_in[2];   // [C, D, D]
    const int*   lab  = (const int*)d_in[3];     // [C, K]
    float* out = (float*)d_out;

    static int smem_set = 0;
    if (!smem_set) {
        cudaFuncSetAttribute(main_kernel,
                             cudaFuncAttributeMaxDynamicSharedMemorySize, SMEM_SZ);
        smem_set = 1;
    }
    prep_kernel<<<Cn, 32>>>(mu, Sinv, lab);
    main_kernel<<<Bn / ROWS, THREADS, SMEM_SZ>>>(data, out);
}

// round 6
// speedup vs baseline: 4.2551x; 1.1508x over previous
#include <cuda_runtime.h>
#include <cuda_fp16.h>

// ---------------- problem constants ----------------
#define Bn 65536
#define Cn 128
#define Dn 32
#define Kn 10
#define NAUG 33
#define KPAD 576          // padded triangular size (9 chunks of 64)
#define KC 64
#define NCH 9
#define ROWS 128
#define THREADS 512
#define TILE_B 16384      // 128 rows x 64 k x fp16 (128B rows, SW128)

#define SWZ(o) ((o) ^ (((o) >> 3) & 0x70))

// pre-split fp16 U tiles, pre-swizzled: [split][chunk][16KB]
__device__ __align__(16) unsigned char g_Uh[2][NCH][TILE_B];
__device__ int g_ij[KPAD];     // (i | j<<8)
__device__ int g_cls[Cn];

// ---------------- helpers ----------------
static __device__ __forceinline__ unsigned smem_u32(const void* p) {
    unsigned a;
    asm("{ .reg .u64 t; cvta.to.shared.u64 t, %1; cvt.u32.u64 %0, t; }"
        : "=r"(a) : "l"(p));
    return a;
}
static __device__ __forceinline__ void cp16(unsigned sdst, const void* gsrc) {
    asm volatile("cp.async.cg.shared.global [%0], [%1], 16;" :: "r"(sdst), "l"(gsrc));
}
static __device__ __forceinline__ void ldsm4(unsigned base, int row0, int kb,
                                             int lane, unsigned* r) {
    unsigned off = (unsigned)((row0 + (lane & 15)) * 128 + kb + ((lane >> 4) << 4));
    unsigned addr = base + SWZ(off);
    asm volatile("ldmatrix.sync.aligned.m8n8.x4.shared.b16 {%0,%1,%2,%3}, [%4];"
                 : "=r"(r[0]), "=r"(r[1]), "=r"(r[2]), "=r"(r[3]) : "r"(addr));
}
#define MMA16816(C, A, b0, b1) \
    asm volatile("mma.sync.aligned.m16n8k16.row.col.f32.f16.f16.f32 " \
        "{%0,%1,%2,%3}, {%4,%5,%6,%7}, {%8,%9}, {%0,%1,%2,%3};" \
        : "+f"((C)[0]), "+f"((C)[1]), "+f"((C)[2]), "+f"((C)[3]) \
        : "r"((A)[0]), "r"((A)[1]), "r"((A)[2]), "r"((A)[3]), "r"(b0), "r"(b1))

// ---------------- prep: split U into 2 fp16 tiles (pre-swizzled) ----------------
__global__ void prep_kernel(const float* __restrict__ mu,
                            const float* __restrict__ S,
                            const int* __restrict__ lab) {
    const int c = blockIdx.x;
    const int t = threadIdx.x;   // 32
    __shared__ float mus[Dn], Sm[Dn];

    mus[t] = mu[c * Dn + t];
    __syncwarp();
    float s = 0.f;
#pragma unroll
    for (int e = 0; e < Dn; e++) s += S[(c * Dn + t) * Dn + e] * mus[e];
    Sm[t] = s;
    __syncwarp();
    float t3 = mus[t] * Sm[t];
#pragma unroll
    for (int m = 16; m >= 1; m >>= 1) t3 += __shfl_xor_sync(0xffffffffu, t3, m);

    if (t == 0) {
        int cl = 0;
        for (int k = 0; k < Kn; k++) if (lab[c * Kn + k] != 0) cl = k;
        g_cls[c] = cl;
    }

    for (int k = t; k < KPAD; k += 32) {
        int i = 0, rem = k;
        while (i < NAUG && rem >= NAUG - i) { rem -= NAUG - i; i++; }
        float v; int ii, jj;
        if (i >= NAUG) { v = 0.f; ii = 32; jj = 32; }
        else {
            int j = i + rem; ii = i; jj = j;
            if (j < Dn)      v = ((i == j) ? 1.f : 2.f) * S[(c * Dn + i) * Dn + j];
            else if (i < Dn) v = -2.f * Sm[i];
            else             v = t3;
        }
        if (c == 0) g_ij[k] = ii | (jj << 8);

        __half h0 = __float2half_rn(v);
        float r = v - __half2float(h0);
        __half h1 = __float2half_rn(r);

        int ch = k >> 6, kk = k & 63;
        int sw = SWZ(c * 128 + kk * 2);
        *(__half*)&g_Uh[0][ch][sw] = h0;
        *(__half*)&g_Uh[1][ch][sw] = h1;
    }
}

// ---------------- smem layout (bytes) ----------------
#define OFF_Z    0          // 33*129*4 = 17028 -> 17152
#define OFF_IJ   17152      // 2304 -> 19456
#define OFF_CLS  19456      // 512 -> 19968
#define OFF_LAB  19968      // 5120 -> 25088
#define OFF_T    25600      // A double (64KB) + B double (64KB)
#define SMEM_SZ  156672

// ---------------- main kernel ----------------
__global__ void __launch_bounds__(THREADS, 1)
main_kernel(const float* __restrict__ data, float* __restrict__ out) {
    extern __shared__ char sm_[];
    int*   ij_s  = (int*)(sm_ + OFF_IJ);
    int*   cls_s = (int*)(sm_ + OFF_CLS);
    float* lab_s = (float*)(sm_ + OFF_LAB);
    float* z_s   = (float*)(sm_ + OFF_Z);

    const int tid = threadIdx.x;
    const int wid = tid >> 5;
    const int lane = tid & 31;
    const int mw = wid >> 2;          // 0..3 -> rows mw*32
    const int nw = wid & 3;           // 0..3 -> cols nw*32
    const int bbase = blockIdx.x * ROWS;
    const unsigned sbase = smem_u32(sm_);

    const unsigned tAbase = sbase + OFF_T;              // + bufA*32768 + split*16384
    const unsigned tBbase = tAbase + 2 * 32768;         // + bufB*32768 + split*16384

    // prologue
    if (tid < Cn) cls_s[tid] = g_cls[tid];
    for (int i = tid; i < Kn * ROWS; i += THREADS) lab_s[i] = 0.f;
    for (int i = tid; i < KPAD; i += THREADS) ij_s[i] = g_ij[i];
    for (int idx = tid; idx < ROWS * Dn; idx += THREADS) {
        int row = idx >> 5, d = idx & 31;
        z_s[d * 129 + row] = data[(size_t)(bbase + row) * Dn + d];
    }
    if (tid < ROWS) z_s[32 * 129 + tid] = 1.f;

    // prefetch B chunk 0 into buf 0
#pragma unroll
    for (int s = 0; s < 2; s++)
        for (int e = tid; e < TILE_B / 16; e += THREADS)
            cp16(tBbase + s * TILE_B + e * 16, &g_Uh[s][0][e * 16]);
    asm volatile("cp.async.commit_group;");
    __syncthreads();   // z_s / ij_s ready

    // build A chunk 0 into buf 0 (8 cells/thread; cell = (row, kpair))
#pragma unroll
    for (int it = 0; it < 8; it++) {
        int idx = tid + it * THREADS;
        int kp = idx & 31, row = idx >> 5;
        int ij0 = ij_s[2 * kp], ij1 = ij_s[2 * kp + 1];
        float w0 = z_s[(ij0 & 255) * 129 + row] * z_s[(ij0 >> 8) * 129 + row];
        float w1 = z_s[(ij1 & 255) * 129 + row] * z_s[(ij1 >> 8) * 129 + row];
        __half h00 = __float2half_rn(w0), h01 = __float2half_rn(w1);
        float r0 = w0 - __half2float(h00);
        float r1 = w1 - __half2float(h01);
        __half2 p0 = __halves2half2(h00, h01);
        __half2 p1 = __halves2half2(__float2half_rn(r0), __float2half_rn(r1));
        unsigned sw = SWZ((unsigned)(row * 128 + kp * 4));
        asm volatile("st.shared.b32 [%0], %1;" :: "r"(tAbase + sw),
                     "r"(*(unsigned*)&p0));
        asm volatile("st.shared.b32 [%0], %1;" :: "r"(tAbase + TILE_B + sw),
                     "r"(*(unsigned*)&p1));
    }

    float acc[8][4];
#pragma unroll
    for (int i = 0; i < 8; i++)
#pragma unroll
        for (int q = 0; q < 4; q++) acc[i][q] = 0.f;

    for (int ch = 0; ch < NCH; ch++) {
        const int cur = ch & 1;
        if (ch + 1 < NCH) {
            unsigned dst = tBbase + (1 - cur) * 32768;
#pragma unroll
            for (int s = 0; s < 2; s++)
                for (int e = tid; e < TILE_B / 16; e += THREADS)
                    cp16(dst + s * TILE_B + e * 16, &g_Uh[s][ch + 1][e * 16]);
            asm volatile("cp.async.commit_group;");
            asm volatile("cp.async.wait_group 1;");
        } else {
            asm volatile("cp.async.wait_group 0;");
        }
        __syncthreads();   // B[cur] visible; A[cur] build (prev chunk) complete

        const unsigned A0 = tAbase + cur * 32768;
        const unsigned A1 = A0 + TILE_B;
        const unsigned B0 = tBbase + cur * 32768;
        const unsigned B1 = B0 + TILE_B;
        const unsigned An0 = tAbase + (1 - cur) * 32768;   // A[next] build target
        const unsigned An1 = An0 + TILE_B;
        const int k0n = (ch + 1) * KC;

#pragma unroll
        for (int ks = 0; ks < 4; ks++) {
            const int kb = ks * 32;
            unsigned a0[2][4], a1[2][4];
#pragma unroll
            for (int mf = 0; mf < 2; mf++) {
                ldsm4(A0, mw * 32 + mf * 16, kb, lane, a0[mf]);
                ldsm4(A1, mw * 32 + mf * 16, kb, lane, a1[mf]);
            }
#pragma unroll
            for (int nf2 = 0; nf2 < 2; nf2++) {
                unsigned b0[4], b1[4];
                ldsm4(B0, nw * 32 + nf2 * 16, kb, lane, b0);
                ldsm4(B1, nw * 32 + nf2 * 16, kb, lane, b1);
#pragma unroll
                for (int mf = 0; mf < 2; mf++)
#pragma unroll
                    for (int h = 0; h < 2; h++) {
                        float* C = acc[mf * 4 + nf2 * 2 + h];
                        MMA16816(C, a0[mf], b0[h], b0[h + 2]);   // h0*g0
                        MMA16816(C, a0[mf], b1[h], b1[h + 2]);   // h0*g1
                        MMA16816(C, a1[mf], b0[h], b0[h + 2]);   // h1*g0
                    }
            }
            // fused: build 2 cells of A[next] (overlaps tensor work)
            if (ch + 1 < NCH) {
#pragma unroll
                for (int t2 = 0; t2 < 2; t2++) {
                    int idx = tid + (ks * 2 + t2) * THREADS;
                    int kp = idx & 31, row = idx >> 5;
                    int ij0 = ij_s[k0n + 2 * kp], ij1 = ij_s[k0n + 2 * kp + 1];
                    float w0 = z_s[(ij0 & 255) * 129 + row] * z_s[(ij0 >> 8) * 129 + row];
                    float w1 = z_s[(ij1 & 255) * 129 + row] * z_s[(ij1 >> 8) * 129 + row];
                    __half h00 = __float2half_rn(w0), h01 = __float2half_rn(w1);
                    float r0 = w0 - __half2float(h00);
                    float r1 = w1 - __half2float(h01);
                    __half2 p0 = __halves2half2(h00, h01);
                    __half2 p1 = __halves2half2(__float2half_rn(r0), __float2half_rn(r1));
                    unsigned sw = SWZ((unsigned)(row * 128 + kp * 4));
                    asm volatile("st.shared.b32 [%0], %1;" :: "r"(An0 + sw),
                                 "r"(*(unsigned*)&p0));
                    asm volatile("st.shared.b32 [%0], %1;" :: "r"(An1 + sw),
                                 "r"(*(unsigned*)&p1));
                }
            }
        }
    }
    __syncthreads();   // all mma done -> tile smem reusable

    // ---------------- epilogue ----------------
    float* gsm = (float*)(sm_ + OFF_T);   // d2 staging [128][130]
    const int lr = lane >> 2, lc = (lane & 3) * 2;
#pragma unroll
    for (int mf = 0; mf < 2; mf++)
#pragma unroll
        for (int nf2 = 0; nf2 < 2; nf2++)
#pragma unroll
            for (int h = 0; h < 2; h++) {
                int row = mw * 32 + mf * 16 + lr;
                int col = nw * 32 + nf2 * 16 + h * 8 + lc;
                float* C = acc[mf * 4 + nf2 * 2 + h];
                gsm[row * 130 + col]           = C[0];
                gsm[row * 130 + col + 1]       = C[1];
                gsm[(row + 8) * 130 + col]     = C[2];
                gsm[(row + 8) * 130 + col + 1] = C[3];
            }
    __syncthreads();

    if (tid < ROWS) {
        const int row = tid;
        float sum = 0.f, gmax = -1.f;
        int cmax = 0;
#pragma unroll 4
        for (int c = 0; c < Cn; c++) {
            float d2 = gsm[row * 130 + c];
            float g = __expf(-0.5f * d2);
            sum += g;
            if (g > gmax) { gmax = g; cmax = c; }
            lab_s[cls_s[c] * ROWS + row] += g;   // row-exclusive
        }
        const size_t b = (size_t)bbase + row;
        float inv = 1.f / (sum + 1e-12f);
        float best = -1.f;
        int kb = 0;
#pragma unroll
        for (int k = 0; k < Kn; k++) {
            float ls = lab_s[k * ROWS + row] * inv;
            out[b * Kn + k] = ls;
            if (ls > best) { best = ls; kb = k; }
        }
        out[(size_t)Bn * Kn + b] = (float)kb;
        out[(size_t)Bn * Kn + Bn + b] = (float)cmax;
    }
}

extern "C" void kernel_launch(void* const* d_in, const int* in_sizes, int n_in,
                              void* d_out, int out_size) {
    const float* data = (const float*)d_in[0];   // [B, D]
    const float* mu   = (const float*)d_in[1];   // [C, D]
    const float* Sinv = (const float*)d_in[2];   // [C, D, D]
    const int*   lab  = (const int*)d_in[3];     // [C, K]
    float* out = (float*)d_out;

    static int smem_set = 0;
    if (!smem_set) {
        cudaFuncSetAttribute(main_kernel,
                             cudaFuncAttributeMaxDynamicSharedMemorySize, SMEM_SZ);
        smem_set = 1;
    }
    prep_kernel<<<Cn, 32>>>(mu, Sinv, lab);
    main_kernel<<<Bn / ROWS, THREADS, SMEM_SZ>>>(data, out);
}